// round 15
// baseline (speedup 1.0000x reference)
#include <cuda_runtime.h>
#include <cuda_fp16.h>
#include <mma.h>
#include <stdint.h>
#include <math.h>

using namespace nvcuda;

// Problem constants
#define BATCH   64
#define NSEQ    196
#define CDIM    1024
#define NHEAD   32
#define HDIM    32
#define MROWS   12544            // BATCH*NSEQ
#define QKVN    3072             // 3*CDIM

// ---------------------------------------------------------------------------
// Static scratch (no cudaMalloc allowed)
// ---------------------------------------------------------------------------
__device__ float g_qkv[(size_t)MROWS * QKVN];       // [12544, 3072] fp32
__device__ __half g_xh[(size_t)MROWS * CDIM];       // x in fp16
__device__ __half g_wqh[(size_t)QKVN * CDIM];       // W_qkv^T [3072,1024] fp16 (Q rows prescaled)
__device__ __half g_wph[(size_t)CDIM * CDIM];       // W_proj^T [1024,1024] fp16
__device__ __half g_ath[(size_t)MROWS * CDIM];      // attention out fp16

// ---------------------------------------------------------------------------
// helpers
// ---------------------------------------------------------------------------
__device__ __forceinline__ uint32_t smem_u32(const void* p) {
    uint32_t a;
    asm("{ .reg .u64 t; cvta.to.shared.u64 t, %1; cvt.u32.u64 %0, t; }"
        : "=r"(a) : "l"(p));
    return a;
}
__device__ __forceinline__ void cp16(uint32_t dst, const void* src) {
    asm volatile("cp.async.cg.shared.global [%0], [%1], 16;\n"
                 :: "r"(dst), "l"(src));
}

// packed f32x2 (PTX ISA, sm_100+ family-common)
__device__ __forceinline__ unsigned long long fma2(
    unsigned long long a, unsigned long long b, unsigned long long c) {
    unsigned long long d;
    asm("fma.rn.f32x2 %0, %1, %2, %3;" : "=l"(d) : "l"(a), "l"(b), "l"(c));
    return d;
}
__device__ __forceinline__ unsigned long long pack2(float x, float y) {
    unsigned long long r;
    asm("mov.b64 %0, {%1, %2};" : "=l"(r) : "f"(x), "f"(y));
    return r;
}
__device__ __forceinline__ float2 unpack2(unsigned long long v) {
    float2 r;
    asm("mov.b64 {%0, %1}, %2;" : "=f"(r.x), "=f"(r.y) : "l"(v));
    return r;
}

// ---------------------------------------------------------------------------
// conversion kernels
// ---------------------------------------------------------------------------
__global__ __launch_bounds__(256) void convert4_kernel(
    const float* __restrict__ in, __half* __restrict__ out)
{
    const size_t i0 = ((size_t)blockIdx.x * 256 + threadIdx.x) * 4;
    const float4 v = *(const float4*)(in + i0);
    *(__half2*)(out + i0)     = __halves2half2(__float2half(v.x), __float2half(v.y));
    *(__half2*)(out + i0 + 2) = __halves2half2(__float2half(v.z), __float2half(v.w));
}

// in: [K, N] fp32 row-major  ->  out: [N, K] fp16 row-major.
// Rows n < qlimit are multiplied by qscale before the (single) fp16 rounding.
__global__ __launch_bounds__(256) void transpose_cvt_kernel(
    const float* __restrict__ in, __half* __restrict__ out, int K, int N,
    int qlimit, float qscale)
{
    __shared__ float t[32][33];
    const int bx = blockIdx.x;   // tile over N
    const int by = blockIdx.y;   // tile over K
    const int x = bx * 32 + threadIdx.x;
    #pragma unroll
    for (int i = 0; i < 32; i += 8) {
        const int y = by * 32 + threadIdx.y + i;
        t[threadIdx.y + i][threadIdx.x] = in[(size_t)y * N + x];
    }
    __syncthreads();
    const int k = by * 32 + threadIdx.x;
    #pragma unroll
    for (int i = 0; i < 32; i += 8) {
        const int n = bx * 32 + threadIdx.y + i;
        float v = t[threadIdx.x][threadIdx.y + i];
        if (n < qlimit) v *= qscale;
        out[(size_t)n * K + k] = __float2half(v);
    }
}

// ---------------------------------------------------------------------------
// HMMA fp16 GEMM: C[M,N] = A*B^T (+bias).
// 128x128 CTA tile, BK=32, 4 warps (2x2), warp tile 64x64.
// 3-STAGE cp.async pipeline, ONE barrier per K-iteration:
//   load target (kt+2)%3 was last read in iteration kt-1; every warp passed
//   this iteration's barrier only after finishing kt-1's compute -> no hazard.
// ---------------------------------------------------------------------------
#define BK       32
#define LDA      40                          // fp16 leading dim (80 B)
#define MAT_T    (128 * LDA * 2)             // 10240 B per matrix tile
#define STAGE_B  (2 * MAT_T)                 // 20480 B (A, B)
#define NSTAGE   3
#define LDC      132
#define GEMM_SMEM (128 * LDC * 4)            // 67584 B (> 3*STAGE_B = 61440)

__global__ __launch_bounds__(128, 3) void gemm_fp16(
    const __half* __restrict__ A, const __half* __restrict__ B,
    float* __restrict__ C, const float* __restrict__ bias,
    int M, int N, int K)
{
    extern __shared__ char smem[];
    const uint32_t sb = smem_u32(smem);
    const int tid = threadIdx.x;
    const int wid = tid >> 5;
    const int lane = tid & 31;
    const int wm = wid >> 1;
    const int wn = wid & 1;
    const int m0 = blockIdx.y * 128;
    const int n0 = blockIdx.x * 128;
    const int NK = K / BK;

    uint32_t doff[4];
    size_t goffA[4], goffB[4];
    #pragma unroll
    for (int it = 0; it < 4; it++) {
        const int id  = it * 128 + tid;
        const int row = id >> 2;
        const int seg = (id & 3) * 16;
        doff[it]  = row * (LDA * 2) + seg;
        goffA[it] = ((size_t)(m0 + row) * K) * 2 + seg;
        goffB[it] = ((size_t)(n0 + row) * K) * 2 + seg;
    }

    auto load_stage = [&](int s, int kc) {
        const uint32_t base = sb + s * STAGE_B;
        const size_t kb = (size_t)kc * (BK * 2);
        #pragma unroll
        for (int it = 0; it < 4; it++) {
            cp16(base + doff[it],         (const char*)A + goffA[it] + kb);
            cp16(base + MAT_T + doff[it], (const char*)B + goffB[it] + kb);
        }
        asm volatile("cp.async.commit_group;" ::: "memory");
    };

    wmma::fragment<wmma::accumulator, 16, 16, 16, float> acc[4][4];
    #pragma unroll
    for (int i = 0; i < 4; i++)
        #pragma unroll
        for (int j = 0; j < 4; j++)
            wmma::fill_fragment(acc[i][j], 0.0f);

    load_stage(0, 0);
    load_stage(1, 1);

    int stage = 0;
    for (int kt = 0; kt < NK; kt++) {
        asm volatile("cp.async.wait_group 1;" ::: "memory");
        __syncthreads();    // the only barrier per iteration

        const char* stg = smem + stage * STAGE_B;
        const __half* Ash = (const __half*)(stg);
        const __half* Bsh = (const __half*)(stg + MAT_T);

        #pragma unroll
        for (int ks = 0; ks < BK; ks += 16) {
            wmma::fragment<wmma::matrix_a, 16, 16, 16, __half, wmma::row_major> af[4];
            #pragma unroll
            for (int i = 0; i < 4; i++) {
                const int r = wm * 64 + i * 16;
                wmma::load_matrix_sync(af[i], Ash + r * LDA + ks, LDA);
            }
            #pragma unroll
            for (int j = 0; j < 4; j++) {
                wmma::fragment<wmma::matrix_b, 16, 16, 16, __half, wmma::col_major> bf;
                const int c = wn * 64 + j * 16;
                wmma::load_matrix_sync(bf, Bsh + c * LDA + ks, LDA);
                #pragma unroll
                for (int i = 0; i < 4; i++)
                    wmma::mma_sync(acc[i][j], af[i], bf, acc[i][j]);
            }
        }

        // load kt+2 into stage (kt+2)%3 — not being read by anyone now
        if (kt + 2 < NK) {
            int ls = stage + 2;
            if (ls >= NSTAGE) ls -= NSTAGE;
            load_stage(ls, kt + 2);
        } else {
            asm volatile("cp.async.commit_group;" ::: "memory");
        }

        if (++stage == NSTAGE) stage = 0;
    }

    // epilogue: frags -> smem (fp32, LDC=132), then bias add + coalesced store
    __syncthreads();
    float* Csh = (float*)smem;
    #pragma unroll
    for (int i = 0; i < 4; i++)
        #pragma unroll
        for (int j = 0; j < 4; j++)
            wmma::store_matrix_sync(
                Csh + (wm * 64 + i * 16) * LDC + wn * 64 + j * 16,
                acc[i][j], LDC, wmma::mem_row_major);
    __syncthreads();

    float4 bb = make_float4(0.f, 0.f, 0.f, 0.f);
    if (bias) bb = *(const float4*)(bias + n0 + lane * 4);
    #pragma unroll 4
    for (int i = 0; i < 32; i++) {
        const int r = wid * 32 + i;
        float4 v = *(const float4*)(Csh + r * LDC + lane * 4);
        v.x += bb.x; v.y += bb.y; v.z += bb.z; v.w += bb.w;
        *(float4*)(C + (size_t)(m0 + r) * N + n0 + lane * 4) = v;
    }
}

// ---------------------------------------------------------------------------
// Fused attention (SIMT + f32x2, 2 rows/thread): one block per (b,h),
// 128 threads (98 active), rows r and r+98.  V/bias prefetched; K loaded
// per-j (no k-next rotation — kept under the register spill cliff).
// Q is pre-scaled (folded into W_qkv).
// ---------------------------------------------------------------------------
#define ATT_THREADS 128
#define ATT_SMEM    ((2 * NSEQ * HDIM + 729) * (int)sizeof(float))   // 53092 B

__global__ __launch_bounds__(ATT_THREADS) void attention_kernel(
    const float* __restrict__ qkv,       // [12544, 3072]
    const float* __restrict__ rpk,       // [729, 32]
    __half* __restrict__ ath)            // [12544, 1024] fp16
{
    extern __shared__ float smf[];
    float* Ksh = smf;
    float* Vsh = smf + NSEQ * HDIM;
    float* rsh = smf + 2 * NSEQ * HDIM;

    const int h   = blockIdx.x;
    const int b   = blockIdx.y;
    const int tid = threadIdx.x;

    const float* base = qkv + (size_t)b * NSEQ * QKVN + h * HDIM;

    for (int f = tid; f < NSEQ * 8; f += ATT_THREADS) {
        const int j  = f >> 3;
        const int d4 = (f & 7) * 4;
        const size_t row = (size_t)j * QKVN;
        *(float4*)(Ksh + j * HDIM + d4) = *(const float4*)(base + row + CDIM   + d4);
        *(float4*)(Vsh + j * HDIM + d4) = *(const float4*)(base + row + 2*CDIM + d4);
    }
    for (int i = tid; i < 729; i += ATT_THREADS)
        rsh[i] = rpk[(size_t)i * HDIM + h];
    __syncthreads();

    if (tid < 98) {
        const int ra = tid;
        const int rb = tid + 98;

        unsigned long long qa[16], qb[16];
        #pragma unroll
        for (int d4 = 0; d4 < 8; d4++) {
            const float4 va = *(const float4*)(base + (size_t)ra * QKVN + d4 * 4);
            qa[d4 * 2 + 0] = pack2(va.x, va.y);
            qa[d4 * 2 + 1] = pack2(va.z, va.w);
            const float4 vb = *(const float4*)(base + (size_t)rb * QKVN + d4 * 4);
            qb[d4 * 2 + 0] = pack2(vb.x, vb.y);
            qb[d4 * 2 + 1] = pack2(vb.z, vb.w);
        }

        unsigned long long aa[16], ab[16];
        #pragma unroll
        for (int i = 0; i < 16; i++) { aa[i] = 0ull; ab[i] = 0ull; }
        float dena = 0.0f, denb = 0.0f;

        const int dyca = (ra / 14 + 13) * 27 + (ra % 14) + 13;
        const int dycb = (rb / 14 + 13) * 27 + (rb % 14) + 13;
        int t = 0, xj = 0;

        for (int j = 0; j < NSEQ; j++) {
            // bias prefetch (LDS latency hides under the QK fma stream)
            const float bia = rsh[dyca - t];
            const float bib = rsh[dycb - t];

            const ulonglong2* kp = (const ulonglong2*)(Ksh + j * HDIM);
            const ulonglong2 k0 = kp[0], k1 = kp[1], k2 = kp[2], k3 = kp[3];
            const ulonglong2 k4 = kp[4], k5 = kp[5], k6 = kp[6], k7 = kp[7];

            unsigned long long s0 = 0ull, s1 = 0ull, s2 = 0ull, s3 = 0ull;
            unsigned long long u0 = 0ull, u1 = 0ull, u2 = 0ull, u3 = 0ull;
            s0 = fma2(qa[0],  k0.x, s0);  u0 = fma2(qb[0],  k0.x, u0);
            s1 = fma2(qa[1],  k0.y, s1);  u1 = fma2(qb[1],  k0.y, u1);
            s2 = fma2(qa[2],  k1.x, s2);  u2 = fma2(qb[2],  k1.x, u2);
            s3 = fma2(qa[3],  k1.y, s3);  u3 = fma2(qb[3],  k1.y, u3);
            s0 = fma2(qa[4],  k2.x, s0);  u0 = fma2(qb[4],  k2.x, u0);
            s1 = fma2(qa[5],  k2.y, s1);  u1 = fma2(qb[5],  k2.y, u1);
            s2 = fma2(qa[6],  k3.x, s2);  u2 = fma2(qb[6],  k3.x, u2);
            s3 = fma2(qa[7],  k3.y, s3);  u3 = fma2(qb[7],  k3.y, u3);
            s0 = fma2(qa[8],  k4.x, s0);  u0 = fma2(qb[8],  k4.x, u0);
            s1 = fma2(qa[9],  k4.y, s1);  u1 = fma2(qb[9],  k4.y, u1);
            s2 = fma2(qa[10], k5.x, s2);  u2 = fma2(qb[10], k5.x, u2);
            s3 = fma2(qa[11], k5.y, s3);  u3 = fma2(qb[11], k5.y, u3);
            s0 = fma2(qa[12], k6.x, s0);  u0 = fma2(qb[12], k6.x, u0);
            s1 = fma2(qa[13], k6.y, s1);  u1 = fma2(qb[13], k6.y, u1);
            s2 = fma2(qa[14], k7.x, s2);  u2 = fma2(qb[14], k7.x, u2);
            s3 = fma2(qa[15], k7.y, s3);  u3 = fma2(qb[15], k7.y, u3);

            // prefetch V(j) — latency overlaps the reduce/exp below
            const ulonglong2* vp = (const ulonglong2*)(Vsh + j * HDIM);
            const ulonglong2 v0 = vp[0], v1 = vp[1], v2 = vp[2], v3 = vp[3];
            const ulonglong2 v4 = vp[4], v5 = vp[5], v6 = vp[6], v7 = vp[7];

            // reduce + bias + exp
            const float2 sa0 = unpack2(s0), sa1 = unpack2(s1);
            const float2 sa2 = unpack2(s2), sa3 = unpack2(s3);
            const float sa = ((sa0.x + sa0.y) + (sa1.x + sa1.y))
                           + ((sa2.x + sa2.y) + (sa3.x + sa3.y));
            const float2 sb0 = unpack2(u0), sb1 = unpack2(u1);
            const float2 sb2 = unpack2(u2), sb3 = unpack2(u3);
            const float sb = ((sb0.x + sb0.y) + (sb1.x + sb1.y))
                           + ((sb2.x + sb2.y) + (sb3.x + sb3.y));

            const float pa = __expf(sa + bia);
            const float pb = __expf(sb + bib);
            dena += pa;
            denb += pb;
            const unsigned long long ppa = pack2(pa, pa);
            const unsigned long long ppb = pack2(pb, pb);

            aa[0]  = fma2(ppa, v0.x, aa[0]);   ab[0]  = fma2(ppb, v0.x, ab[0]);
            aa[1]  = fma2(ppa, v0.y, aa[1]);   ab[1]  = fma2(ppb, v0.y, ab[1]);
            aa[2]  = fma2(ppa, v1.x, aa[2]);   ab[2]  = fma2(ppb, v1.x, ab[2]);
            aa[3]  = fma2(ppa, v1.y, aa[3]);   ab[3]  = fma2(ppb, v1.y, ab[3]);
            aa[4]  = fma2(ppa, v2.x, aa[4]);   ab[4]  = fma2(ppb, v2.x, ab[4]);
            aa[5]  = fma2(ppa, v2.y, aa[5]);   ab[5]  = fma2(ppb, v2.y, ab[5]);
            aa[6]  = fma2(ppa, v3.x, aa[6]);   ab[6]  = fma2(ppb, v3.x, ab[6]);
            aa[7]  = fma2(ppa, v3.y, aa[7]);   ab[7]  = fma2(ppb, v3.y, ab[7]);
            aa[8]  = fma2(ppa, v4.x, aa[8]);   ab[8]  = fma2(ppb, v4.x, ab[8]);
            aa[9]  = fma2(ppa, v4.y, aa[9]);   ab[9]  = fma2(ppb, v4.y, ab[9]);
            aa[10] = fma2(ppa, v5.x, aa[10]);  ab[10] = fma2(ppb, v5.x, ab[10]);
            aa[11] = fma2(ppa, v5.y, aa[11]);  ab[11] = fma2(ppb, v5.y, ab[11]);
            aa[12] = fma2(ppa, v6.x, aa[12]);  ab[12] = fma2(ppb, v6.x, ab[12]);
            aa[13] = fma2(ppa, v6.y, aa[13]);  ab[13] = fma2(ppb, v6.y, ab[13]);
            aa[14] = fma2(ppa, v7.x, aa[14]);  ab[14] = fma2(ppb, v7.x, ab[14]);
            aa[15] = fma2(ppa, v7.y, aa[15]);  ab[15] = fma2(ppb, v7.y, ab[15]);

            t++;
            if (++xj == 14) { xj = 0; t += 13; }
        }

        const float inva = 1.0f / dena;
        const float invb = 1.0f / denb;
        __half* oa = ath + (size_t)(b * NSEQ + ra) * CDIM + h * HDIM;
        __half* ob = ath + (size_t)(b * NSEQ + rb) * CDIM + h * HDIM;
        #pragma unroll
        for (int i = 0; i < 16; i++) {
            const float2 o1 = unpack2(aa[i]);
            *(__half2*)(oa + i * 2) = __halves2half2(
                __float2half(o1.x * inva), __float2half(o1.y * inva));
            const float2 o2 = unpack2(ab[i]);
            *(__half2*)(ob + i * 2) = __halves2half2(
                __float2half(o2.x * invb), __float2half(o2.y * invb));
        }
    }
}

// ---------------------------------------------------------------------------
// Launch
// ---------------------------------------------------------------------------
extern "C" void kernel_launch(void* const* d_in, const int* in_sizes, int n_in,
                              void* d_out, int out_size)
{
    const float* x      = (const float*)d_in[0];
    const float* W_qkv  = (const float*)d_in[1];
    const float* W_proj = (const float*)d_in[2];
    const float* b_proj = (const float*)d_in[3];
    const float* rpk    = (const float*)d_in[4];
    float* out = (float*)d_out;

    float *qkv;
    __half *xh, *wqh, *wph, *ath;
    cudaGetSymbolAddress((void**)&qkv, g_qkv);
    cudaGetSymbolAddress((void**)&xh,  g_xh);
    cudaGetSymbolAddress((void**)&wqh, g_wqh);
    cudaGetSymbolAddress((void**)&wph, g_wph);
    cudaGetSymbolAddress((void**)&ath, g_ath);

    cudaFuncSetAttribute(gemm_fp16,
                         cudaFuncAttributeMaxDynamicSharedMemorySize, GEMM_SMEM);
    cudaFuncSetAttribute(attention_kernel,
                         cudaFuncAttributeMaxDynamicSharedMemorySize, ATT_SMEM);

    // 0) conversions (Q rows of W_qkv prescaled by HD^-0.5)
    convert4_kernel<<<MROWS * CDIM / 1024, 256>>>(x, xh);
    transpose_cvt_kernel<<<dim3(QKVN / 32, CDIM / 32), dim3(32, 8)>>>(
        W_qkv, wqh, CDIM, QKVN, CDIM, 0.17677669529663687f);
    transpose_cvt_kernel<<<dim3(CDIM / 32, CDIM / 32), dim3(32, 8)>>>(
        W_proj, wph, CDIM, CDIM, 0, 1.0f);

    // 1) QKV projection: [12544,1024] x [1024,3072]
    gemm_fp16<<<dim3(QKVN / 128, MROWS / 128), 128, GEMM_SMEM>>>(
        xh, wqh, qkv, nullptr, MROWS, QKVN, CDIM);

    // 2) SIMT f32x2 attention per (b,h), 2 rows/thread
    attention_kernel<<<dim3(NHEAD, BATCH), ATT_THREADS, ATT_SMEM>>>(qkv, rpk, ath);

    // 3) output projection: [12544,1024] x [1024,1024] + bias
    gemm_fp16<<<dim3(CDIM / 128, MROWS / 128), 128, GEMM_SMEM>>>(
        ath, wph, out, b_proj, MROWS, CDIM, CDIM);
}

// round 16
// speedup vs baseline: 1.0892x; 1.0892x over previous
#include <cuda_runtime.h>
#include <cuda_fp16.h>
#include <mma.h>
#include <stdint.h>
#include <math.h>

using namespace nvcuda;

// Problem constants
#define BATCH   64
#define NSEQ    196
#define CDIM    1024
#define NHEAD   32
#define HDIM    32
#define MROWS   12544            // BATCH*NSEQ
#define QKVN    3072             // 3*CDIM

// ---------------------------------------------------------------------------
// Static scratch (no cudaMalloc allowed)
// ---------------------------------------------------------------------------
__device__ float g_qkv[(size_t)MROWS * QKVN];       // [12544, 3072] fp32
__device__ __half g_xh[(size_t)MROWS * CDIM];       // x in fp16
__device__ __half g_wqh[(size_t)QKVN * CDIM];       // W_qkv^T [3072,1024] fp16 (Q rows prescaled)
__device__ __half g_wph[(size_t)CDIM * CDIM];       // W_proj^T [1024,1024] fp16
__device__ __half g_ath[(size_t)MROWS * CDIM];      // attention out fp16

// ---------------------------------------------------------------------------
// helpers
// ---------------------------------------------------------------------------
__device__ __forceinline__ uint32_t smem_u32(const void* p) {
    uint32_t a;
    asm("{ .reg .u64 t; cvta.to.shared.u64 t, %1; cvt.u32.u64 %0, t; }"
        : "=r"(a) : "l"(p));
    return a;
}
__device__ __forceinline__ void cp16(uint32_t dst, const void* src) {
    asm volatile("cp.async.cg.shared.global [%0], [%1], 16;\n"
                 :: "r"(dst), "l"(src));
}

// packed f32x2 (PTX ISA, sm_100+ family-common)
__device__ __forceinline__ unsigned long long fma2(
    unsigned long long a, unsigned long long b, unsigned long long c) {
    unsigned long long d;
    asm("fma.rn.f32x2 %0, %1, %2, %3;" : "=l"(d) : "l"(a), "l"(b), "l"(c));
    return d;
}
__device__ __forceinline__ unsigned long long pack2(float x, float y) {
    unsigned long long r;
    asm("mov.b64 %0, {%1, %2};" : "=l"(r) : "f"(x), "f"(y));
    return r;
}
__device__ __forceinline__ float2 unpack2(unsigned long long v) {
    float2 r;
    asm("mov.b64 {%0, %1}, %2;" : "=f"(r.x), "=f"(r.y) : "l"(v));
    return r;
}

// ---------------------------------------------------------------------------
// conversion kernels
// ---------------------------------------------------------------------------
__global__ __launch_bounds__(256) void convert4_kernel(
    const float* __restrict__ in, __half* __restrict__ out)
{
    const size_t i0 = ((size_t)blockIdx.x * 256 + threadIdx.x) * 4;
    const float4 v = *(const float4*)(in + i0);
    *(__half2*)(out + i0)     = __halves2half2(__float2half(v.x), __float2half(v.y));
    *(__half2*)(out + i0 + 2) = __halves2half2(__float2half(v.z), __float2half(v.w));
}

// in: [K, N] fp32 row-major  ->  out: [N, K] fp16 row-major.
// Rows n < qlimit are multiplied by qscale before the (single) fp16 rounding.
__global__ __launch_bounds__(256) void transpose_cvt_kernel(
    const float* __restrict__ in, __half* __restrict__ out, int K, int N,
    int qlimit, float qscale)
{
    __shared__ float t[32][33];
    const int bx = blockIdx.x;   // tile over N
    const int by = blockIdx.y;   // tile over K
    const int x = bx * 32 + threadIdx.x;
    #pragma unroll
    for (int i = 0; i < 32; i += 8) {
        const int y = by * 32 + threadIdx.y + i;
        t[threadIdx.y + i][threadIdx.x] = in[(size_t)y * N + x];
    }
    __syncthreads();
    const int k = by * 32 + threadIdx.x;
    #pragma unroll
    for (int i = 0; i < 32; i += 8) {
        const int n = bx * 32 + threadIdx.y + i;
        float v = t[threadIdx.x][threadIdx.y + i];
        if (n < qlimit) v *= qscale;
        out[(size_t)n * K + k] = __float2half(v);
    }
}

// ---------------------------------------------------------------------------
// HMMA fp16 GEMM: C[M,N] = A*B^T (+bias).
// 128x128 CTA tile, BK=32, 4 warps (2x2), warp tile 64x64.
// 3-STAGE cp.async pipeline, ONE barrier per K-iteration (round-15 proven).
// ---------------------------------------------------------------------------
#define BK       32
#define LDA      40                          // fp16 leading dim (80 B)
#define MAT_T    (128 * LDA * 2)             // 10240 B per matrix tile
#define STAGE_B  (2 * MAT_T)                 // 20480 B (A, B)
#define NSTAGE   3
#define LDC      132
#define GEMM_SMEM (128 * LDC * 4)            // 67584 B (> 3*STAGE_B = 61440)

__global__ __launch_bounds__(128, 3) void gemm_fp16(
    const __half* __restrict__ A, const __half* __restrict__ B,
    float* __restrict__ C, const float* __restrict__ bias,
    int M, int N, int K)
{
    extern __shared__ char smem[];
    const uint32_t sb = smem_u32(smem);
    const int tid = threadIdx.x;
    const int wid = tid >> 5;
    const int lane = tid & 31;
    const int wm = wid >> 1;
    const int wn = wid & 1;
    const int m0 = blockIdx.y * 128;
    const int n0 = blockIdx.x * 128;
    const int NK = K / BK;

    uint32_t doff[4];
    size_t goffA[4], goffB[4];
    #pragma unroll
    for (int it = 0; it < 4; it++) {
        const int id  = it * 128 + tid;
        const int row = id >> 2;
        const int seg = (id & 3) * 16;
        doff[it]  = row * (LDA * 2) + seg;
        goffA[it] = ((size_t)(m0 + row) * K) * 2 + seg;
        goffB[it] = ((size_t)(n0 + row) * K) * 2 + seg;
    }

    auto load_stage = [&](int s, int kc) {
        const uint32_t base = sb + s * STAGE_B;
        const size_t kb = (size_t)kc * (BK * 2);
        #pragma unroll
        for (int it = 0; it < 4; it++) {
            cp16(base + doff[it],         (const char*)A + goffA[it] + kb);
            cp16(base + MAT_T + doff[it], (const char*)B + goffB[it] + kb);
        }
        asm volatile("cp.async.commit_group;" ::: "memory");
    };

    wmma::fragment<wmma::accumulator, 16, 16, 16, float> acc[4][4];
    #pragma unroll
    for (int i = 0; i < 4; i++)
        #pragma unroll
        for (int j = 0; j < 4; j++)
            wmma::fill_fragment(acc[i][j], 0.0f);

    load_stage(0, 0);
    load_stage(1, 1);

    int stage = 0;
    for (int kt = 0; kt < NK; kt++) {
        asm volatile("cp.async.wait_group 1;" ::: "memory");
        __syncthreads();    // the only barrier per iteration

        const char* stg = smem + stage * STAGE_B;
        const __half* Ash = (const __half*)(stg);
        const __half* Bsh = (const __half*)(stg + MAT_T);

        #pragma unroll
        for (int ks = 0; ks < BK; ks += 16) {
            wmma::fragment<wmma::matrix_a, 16, 16, 16, __half, wmma::row_major> af[4];
            #pragma unroll
            for (int i = 0; i < 4; i++) {
                const int r = wm * 64 + i * 16;
                wmma::load_matrix_sync(af[i], Ash + r * LDA + ks, LDA);
            }
            #pragma unroll
            for (int j = 0; j < 4; j++) {
                wmma::fragment<wmma::matrix_b, 16, 16, 16, __half, wmma::col_major> bf;
                const int c = wn * 64 + j * 16;
                wmma::load_matrix_sync(bf, Bsh + c * LDA + ks, LDA);
                #pragma unroll
                for (int i = 0; i < 4; i++)
                    wmma::mma_sync(acc[i][j], af[i], bf, acc[i][j]);
            }
        }

        // load kt+2 into stage (kt+2)%3 — not being read by anyone now
        if (kt + 2 < NK) {
            int ls = stage + 2;
            if (ls >= NSTAGE) ls -= NSTAGE;
            load_stage(ls, kt + 2);
        } else {
            asm volatile("cp.async.commit_group;" ::: "memory");
        }

        if (++stage == NSTAGE) stage = 0;
    }

    // epilogue: frags -> smem (fp32, LDC=132), then bias add + coalesced store
    __syncthreads();
    float* Csh = (float*)smem;
    #pragma unroll
    for (int i = 0; i < 4; i++)
        #pragma unroll
        for (int j = 0; j < 4; j++)
            wmma::store_matrix_sync(
                Csh + (wm * 64 + i * 16) * LDC + wn * 64 + j * 16,
                acc[i][j], LDC, wmma::mem_row_major);
    __syncthreads();

    float4 bb = make_float4(0.f, 0.f, 0.f, 0.f);
    if (bias) bb = *(const float4*)(bias + n0 + lane * 4);
    #pragma unroll 4
    for (int i = 0; i < 32; i++) {
        const int r = wid * 32 + i;
        float4 v = *(const float4*)(Csh + r * LDC + lane * 4);
        v.x += bb.x; v.y += bb.y; v.z += bb.z; v.w += bb.w;
        *(float4*)(C + (size_t)(m0 + r) * N + n0 + lane * 4) = v;
    }
}

// ---------------------------------------------------------------------------
// Fused attention (round-14 proven): SIMT + f32x2, 2 rows/thread,
// software-pipelined with K(j+1) register rotation + V/bias prefetch.
// One block per (b,h), 128 threads (98 active), rows r and r+98.
// Q is pre-scaled (folded into W_qkv).
// ---------------------------------------------------------------------------
#define ATT_THREADS 128
#define ATT_SMEM    ((2 * NSEQ * HDIM + 729) * (int)sizeof(float))   // 53092 B

__global__ __launch_bounds__(ATT_THREADS) void attention_kernel(
    const float* __restrict__ qkv,       // [12544, 3072]
    const float* __restrict__ rpk,       // [729, 32]
    __half* __restrict__ ath)            // [12544, 1024] fp16
{
    extern __shared__ float smf[];
    float* Ksh = smf;
    float* Vsh = smf + NSEQ * HDIM;
    float* rsh = smf + 2 * NSEQ * HDIM;

    const int h   = blockIdx.x;
    const int b   = blockIdx.y;
    const int tid = threadIdx.x;

    const float* base = qkv + (size_t)b * NSEQ * QKVN + h * HDIM;

    for (int f = tid; f < NSEQ * 8; f += ATT_THREADS) {
        const int j  = f >> 3;
        const int d4 = (f & 7) * 4;
        const size_t row = (size_t)j * QKVN;
        *(float4*)(Ksh + j * HDIM + d4) = *(const float4*)(base + row + CDIM   + d4);
        *(float4*)(Vsh + j * HDIM + d4) = *(const float4*)(base + row + 2*CDIM + d4);
    }
    for (int i = tid; i < 729; i += ATT_THREADS)
        rsh[i] = rpk[(size_t)i * HDIM + h];
    __syncthreads();

    if (tid < 98) {
        const int ra = tid;
        const int rb = tid + 98;

        unsigned long long qa[16], qb[16];
        #pragma unroll
        for (int d4 = 0; d4 < 8; d4++) {
            const float4 va = *(const float4*)(base + (size_t)ra * QKVN + d4 * 4);
            qa[d4 * 2 + 0] = pack2(va.x, va.y);
            qa[d4 * 2 + 1] = pack2(va.z, va.w);
            const float4 vb = *(const float4*)(base + (size_t)rb * QKVN + d4 * 4);
            qb[d4 * 2 + 0] = pack2(vb.x, vb.y);
            qb[d4 * 2 + 1] = pack2(vb.z, vb.w);
        }

        unsigned long long aa[16], ab[16];
        #pragma unroll
        for (int i = 0; i < 16; i++) { aa[i] = 0ull; ab[i] = 0ull; }
        float dena = 0.0f, denb = 0.0f;

        const int dyca = (ra / 14 + 13) * 27 + (ra % 14) + 13;
        const int dycb = (rb / 14 + 13) * 27 + (rb % 14) + 13;
        int t = 0, xj = 0;

        // preload K row 0
        ulonglong2 k0, k1, k2, k3, k4, k5, k6, k7;
        {
            const ulonglong2* kp = (const ulonglong2*)Ksh;
            k0 = kp[0]; k1 = kp[1]; k2 = kp[2]; k3 = kp[3];
            k4 = kp[4]; k5 = kp[5]; k6 = kp[6]; k7 = kp[7];
        }

        for (int j = 0; j < NSEQ; j++) {
            // bias prefetch (LDS latency hides under the QK fma stream)
            const float bia = rsh[dyca - t];
            const float bib = rsh[dycb - t];

            // QK for both rows on current K registers
            unsigned long long s0 = 0ull, s1 = 0ull, s2 = 0ull, s3 = 0ull;
            unsigned long long u0 = 0ull, u1 = 0ull, u2 = 0ull, u3 = 0ull;
            s0 = fma2(qa[0],  k0.x, s0);  u0 = fma2(qb[0],  k0.x, u0);
            s1 = fma2(qa[1],  k0.y, s1);  u1 = fma2(qb[1],  k0.y, u1);
            s2 = fma2(qa[2],  k1.x, s2);  u2 = fma2(qb[2],  k1.x, u2);
            s3 = fma2(qa[3],  k1.y, s3);  u3 = fma2(qb[3],  k1.y, u3);
            s0 = fma2(qa[4],  k2.x, s0);  u0 = fma2(qb[4],  k2.x, u0);
            s1 = fma2(qa[5],  k2.y, s1);  u1 = fma2(qb[5],  k2.y, u1);
            s2 = fma2(qa[6],  k3.x, s2);  u2 = fma2(qb[6],  k3.x, u2);
            s3 = fma2(qa[7],  k3.y, s3);  u3 = fma2(qb[7],  k3.y, u3);
            s0 = fma2(qa[8],  k4.x, s0);  u0 = fma2(qb[8],  k4.x, u0);
            s1 = fma2(qa[9],  k4.y, s1);  u1 = fma2(qb[9],  k4.y, u1);
            s2 = fma2(qa[10], k5.x, s2);  u2 = fma2(qb[10], k5.x, u2);
            s3 = fma2(qa[11], k5.y, s3);  u3 = fma2(qb[11], k5.y, u3);
            s0 = fma2(qa[12], k6.x, s0);  u0 = fma2(qb[12], k6.x, u0);
            s1 = fma2(qa[13], k6.y, s1);  u1 = fma2(qb[13], k6.y, u1);
            s2 = fma2(qa[14], k7.x, s2);  u2 = fma2(qb[14], k7.x, u2);
            s3 = fma2(qa[15], k7.y, s3);  u3 = fma2(qb[15], k7.y, u3);

            // prefetch V(j) and K(j+1) — latency overlaps the reduce/exp below
            const ulonglong2* vp = (const ulonglong2*)(Vsh + j * HDIM);
            const ulonglong2 v0 = vp[0], v1 = vp[1], v2 = vp[2], v3 = vp[3];
            const ulonglong2 v4 = vp[4], v5 = vp[5], v6 = vp[6], v7 = vp[7];
            const int jn = (j + 1 < NSEQ) ? (j + 1) : 0;
            const ulonglong2* kpn = (const ulonglong2*)(Ksh + jn * HDIM);
            const ulonglong2 n0 = kpn[0], n1 = kpn[1], n2 = kpn[2], n3 = kpn[3];
            const ulonglong2 n4 = kpn[4], n5 = kpn[5], n6 = kpn[6], n7 = kpn[7];

            // reduce + bias + exp
            const float2 sa0 = unpack2(s0), sa1 = unpack2(s1);
            const float2 sa2 = unpack2(s2), sa3 = unpack2(s3);
            const float sa = ((sa0.x + sa0.y) + (sa1.x + sa1.y))
                           + ((sa2.x + sa2.y) + (sa3.x + sa3.y));
            const float2 sb0 = unpack2(u0), sb1 = unpack2(u1);
            const float2 sb2 = unpack2(u2), sb3 = unpack2(u3);
            const float sb = ((sb0.x + sb0.y) + (sb1.x + sb1.y))
                           + ((sb2.x + sb2.y) + (sb3.x + sb3.y));

            const float pa = __expf(sa + bia);
            const float pb = __expf(sb + bib);
            dena += pa;
            denb += pb;
            const unsigned long long ppa = pack2(pa, pa);
            const unsigned long long ppb = pack2(pb, pb);

            // PV on prefetched V registers
            aa[0]  = fma2(ppa, v0.x, aa[0]);   ab[0]  = fma2(ppb, v0.x, ab[0]);
            aa[1]  = fma2(ppa, v0.y, aa[1]);   ab[1]  = fma2(ppb, v0.y, ab[1]);
            aa[2]  = fma2(ppa, v1.x, aa[2]);   ab[2]  = fma2(ppb, v1.x, ab[2]);
            aa[3]  = fma2(ppa, v1.y, aa[3]);   ab[3]  = fma2(ppb, v1.y, ab[3]);
            aa[4]  = fma2(ppa, v2.x, aa[4]);   ab[4]  = fma2(ppb, v2.x, ab[4]);
            aa[5]  = fma2(ppa, v2.y, aa[5]);   ab[5]  = fma2(ppb, v2.y, ab[5]);
            aa[6]  = fma2(ppa, v3.x, aa[6]);   ab[6]  = fma2(ppb, v3.x, ab[6]);
            aa[7]  = fma2(ppa, v3.y, aa[7]);   ab[7]  = fma2(ppb, v3.y, ab[7]);
            aa[8]  = fma2(ppa, v4.x, aa[8]);   ab[8]  = fma2(ppb, v4.x, ab[8]);
            aa[9]  = fma2(ppa, v4.y, aa[9]);   ab[9]  = fma2(ppb, v4.y, ab[9]);
            aa[10] = fma2(ppa, v5.x, aa[10]);  ab[10] = fma2(ppb, v5.x, ab[10]);
            aa[11] = fma2(ppa, v5.y, aa[11]);  ab[11] = fma2(ppb, v5.y, ab[11]);
            aa[12] = fma2(ppa, v6.x, aa[12]);  ab[12] = fma2(ppb, v6.x, ab[12]);
            aa[13] = fma2(ppa, v6.y, aa[13]);  ab[13] = fma2(ppb, v6.y, ab[13]);
            aa[14] = fma2(ppa, v7.x, aa[14]);  ab[14] = fma2(ppb, v7.x, ab[14]);
            aa[15] = fma2(ppa, v7.y, aa[15]);  ab[15] = fma2(ppb, v7.y, ab[15]);

            // rotate K registers
            k0 = n0; k1 = n1; k2 = n2; k3 = n3;
            k4 = n4; k5 = n5; k6 = n6; k7 = n7;

            t++;
            if (++xj == 14) { xj = 0; t += 13; }
        }

        const float inva = 1.0f / dena;
        const float invb = 1.0f / denb;
        __half* oa = ath + (size_t)(b * NSEQ + ra) * CDIM + h * HDIM;
        __half* ob = ath + (size_t)(b * NSEQ + rb) * CDIM + h * HDIM;
        #pragma unroll
        for (int i = 0; i < 16; i++) {
            const float2 o1 = unpack2(aa[i]);
            *(__half2*)(oa + i * 2) = __halves2half2(
                __float2half(o1.x * inva), __float2half(o1.y * inva));
            const float2 o2 = unpack2(ab[i]);
            *(__half2*)(ob + i * 2) = __halves2half2(
                __float2half(o2.x * invb), __float2half(o2.y * invb));
        }
    }
}

// ---------------------------------------------------------------------------
// Launch
// ---------------------------------------------------------------------------
extern "C" void kernel_launch(void* const* d_in, const int* in_sizes, int n_in,
                              void* d_out, int out_size)
{
    const float* x      = (const float*)d_in[0];
    const float* W_qkv  = (const float*)d_in[1];
    const float* W_proj = (const float*)d_in[2];
    const float* b_proj = (const float*)d_in[3];
    const float* rpk    = (const float*)d_in[4];
    float* out = (float*)d_out;

    float *qkv;
    __half *xh, *wqh, *wph, *ath;
    cudaGetSymbolAddress((void**)&qkv, g_qkv);
    cudaGetSymbolAddress((void**)&xh,  g_xh);
    cudaGetSymbolAddress((void**)&wqh, g_wqh);
    cudaGetSymbolAddress((void**)&wph, g_wph);
    cudaGetSymbolAddress((void**)&ath, g_ath);

    cudaFuncSetAttribute(gemm_fp16,
                         cudaFuncAttributeMaxDynamicSharedMemorySize, GEMM_SMEM);
    cudaFuncSetAttribute(attention_kernel,
                         cudaFuncAttributeMaxDynamicSharedMemorySize, ATT_SMEM);

    // 0) conversions (Q rows of W_qkv prescaled by HD^-0.5)
    convert4_kernel<<<MROWS * CDIM / 1024, 256>>>(x, xh);
    transpose_cvt_kernel<<<dim3(QKVN / 32, CDIM / 32), dim3(32, 8)>>>(
        W_qkv, wqh, CDIM, QKVN, CDIM, 0.17677669529663687f);
    transpose_cvt_kernel<<<dim3(CDIM / 32, CDIM / 32), dim3(32, 8)>>>(
        W_proj, wph, CDIM, CDIM, 0, 1.0f);

    // 1) QKV projection: [12544,1024] x [1024,3072]
    gemm_fp16<<<dim3(QKVN / 128, MROWS / 128), 128, GEMM_SMEM>>>(
        xh, wqh, qkv, nullptr, MROWS, QKVN, CDIM);

    // 2) SIMT f32x2 attention per (b,h), 2 rows/thread, k-rotation pipeline
    attention_kernel<<<dim3(NHEAD, BATCH), ATT_THREADS, ATT_SMEM>>>(qkv, rpk, ath);

    // 3) output projection: [12544,1024] x [1024,1024] + bias
    gemm_fp16<<<dim3(CDIM / 128, MROWS / 128), 128, GEMM_SMEM>>>(
        ath, wph, out, b_proj, MROWS, CDIM, CDIM);
}

// round 17
// speedup vs baseline: 1.1069x; 1.0162x over previous
#include <cuda_runtime.h>
#include <cuda_fp16.h>
#include <mma.h>
#include <stdint.h>
#include <math.h>

using namespace nvcuda;

// Problem constants
#define BATCH   64
#define NSEQ    196
#define CDIM    1024
#define NHEAD   32
#define HDIM    32
#define MROWS   12544            // BATCH*NSEQ
#define QKVN    3072             // 3*CDIM

// ---------------------------------------------------------------------------
// Static scratch (no cudaMalloc allowed)
// ---------------------------------------------------------------------------
__device__ float g_qkv[(size_t)MROWS * QKVN];       // [12544, 3072] fp32
__device__ __half g_xh[(size_t)MROWS * CDIM];       // x in fp16
__device__ __half g_wqh[(size_t)QKVN * CDIM];       // W_qkv^T [3072,1024] fp16 (Q rows prescaled)
__device__ __half g_wph[(size_t)CDIM * CDIM];       // W_proj^T [1024,1024] fp16
__device__ __half g_ath[(size_t)MROWS * CDIM];      // attention out fp16

// ---------------------------------------------------------------------------
// helpers
// ---------------------------------------------------------------------------
__device__ __forceinline__ uint32_t smem_u32(const void* p) {
    uint32_t a;
    asm("{ .reg .u64 t; cvta.to.shared.u64 t, %1; cvt.u32.u64 %0, t; }"
        : "=r"(a) : "l"(p));
    return a;
}
__device__ __forceinline__ void cp16(uint32_t dst, const void* src) {
    asm volatile("cp.async.cg.shared.global [%0], [%1], 16;\n"
                 :: "r"(dst), "l"(src));
}

// packed f32x2 (PTX ISA, sm_100+ family-common)
__device__ __forceinline__ unsigned long long fma2(
    unsigned long long a, unsigned long long b, unsigned long long c) {
    unsigned long long d;
    asm("fma.rn.f32x2 %0, %1, %2, %3;" : "=l"(d) : "l"(a), "l"(b), "l"(c));
    return d;
}
__device__ __forceinline__ unsigned long long add2(
    unsigned long long a, unsigned long long b) {
    unsigned long long d;
    asm("add.rn.f32x2 %0, %1, %2;" : "=l"(d) : "l"(a), "l"(b));
    return d;
}
__device__ __forceinline__ unsigned long long pack2(float x, float y) {
    unsigned long long r;
    asm("mov.b64 %0, {%1, %2};" : "=l"(r) : "f"(x), "f"(y));
    return r;
}
__device__ __forceinline__ float2 unpack2(unsigned long long v) {
    float2 r;
    asm("mov.b64 {%0, %1}, %2;" : "=f"(r.x), "=f"(r.y) : "l"(v));
    return r;
}

// ---------------------------------------------------------------------------
// fused conversion kernel: one launch does
//   blocks [0, NB_CVT)                : x fp32 -> fp16        (flat 256 thr)
//   blocks [NB_CVT, NB_CVT+NB_TQ)     : W_qkv transpose+cvt   (Q rows prescaled)
//   blocks [NB_CVT+NB_TQ, ... +NB_TP) : W_proj transpose+cvt
// ---------------------------------------------------------------------------
#define NB_CVT  (MROWS * CDIM / 1024)          // 12544
#define NB_TQ   ((QKVN / 32) * (CDIM / 32))    // 3072
#define NB_TP   ((CDIM / 32) * (CDIM / 32))    // 1024
#define QSCALE  0.17677669529663687f

__device__ __forceinline__ void transpose_cvt_body(
    const float* __restrict__ in, __half* __restrict__ out, int K, int N,
    int bx, int by, int qlimit, float qscale)
{
    __shared__ float t[32][33];
    const int lx = threadIdx.x & 31;
    const int ly = threadIdx.x >> 5;       // 0..7
    const int x = bx * 32 + lx;
    #pragma unroll
    for (int i = 0; i < 32; i += 8) {
        const int y = by * 32 + ly + i;
        t[ly + i][lx] = in[(size_t)y * N + x];
    }
    __syncthreads();
    const int k = by * 32 + lx;
    #pragma unroll
    for (int i = 0; i < 32; i += 8) {
        const int n = bx * 32 + ly + i;
        float v = t[lx][ly + i];
        if (n < qlimit) v *= qscale;
        out[(size_t)n * K + k] = __float2half(v);
    }
}

__global__ __launch_bounds__(256) void fused_convert_kernel(
    const float* __restrict__ x, __half* __restrict__ xh,
    const float* __restrict__ Wq, __half* __restrict__ wqh,
    const float* __restrict__ Wp, __half* __restrict__ wph)
{
    const int bid = blockIdx.x;
    if (bid < NB_CVT) {
        const size_t i0 = ((size_t)bid * 256 + threadIdx.x) * 4;
        const float4 v = *(const float4*)(x + i0);
        *(__half2*)(xh + i0)     = __halves2half2(__float2half(v.x), __float2half(v.y));
        *(__half2*)(xh + i0 + 2) = __halves2half2(__float2half(v.z), __float2half(v.w));
    } else if (bid < NB_CVT + NB_TQ) {
        const int idx = bid - NB_CVT;
        transpose_cvt_body(Wq, wqh, CDIM, QKVN,
                           idx % (QKVN / 32), idx / (QKVN / 32), CDIM, QSCALE);
    } else {
        const int idx = bid - NB_CVT - NB_TQ;
        transpose_cvt_body(Wp, wph, CDIM, CDIM,
                           idx % (CDIM / 32), idx / (CDIM / 32), 0, 1.0f);
    }
}

// ---------------------------------------------------------------------------
// HMMA fp16 GEMM: C[M,N] = A*B^T (+bias).
// 128x128 CTA tile, BK=32, 4 warps (2x2), warp tile 64x64.
// 3-STAGE cp.async pipeline, ONE barrier per K-iteration (round-15 proven).
// ---------------------------------------------------------------------------
#define BK       32
#define LDA      40                          // fp16 leading dim (80 B)
#define MAT_T    (128 * LDA * 2)             // 10240 B per matrix tile
#define STAGE_B  (2 * MAT_T)                 // 20480 B (A, B)
#define NSTAGE   3
#define LDC      132
#define GEMM_SMEM (128 * LDC * 4)            // 67584 B (> 3*STAGE_B = 61440)

__global__ __launch_bounds__(128, 3) void gemm_fp16(
    const __half* __restrict__ A, const __half* __restrict__ B,
    float* __restrict__ C, const float* __restrict__ bias,
    int M, int N, int K)
{
    extern __shared__ char smem[];
    const uint32_t sb = smem_u32(smem);
    const int tid = threadIdx.x;
    const int wid = tid >> 5;
    const int lane = tid & 31;
    const int wm = wid >> 1;
    const int wn = wid & 1;
    const int m0 = blockIdx.y * 128;
    const int n0 = blockIdx.x * 128;
    const int NK = K / BK;

    uint32_t doff[4];
    size_t goffA[4], goffB[4];
    #pragma unroll
    for (int it = 0; it < 4; it++) {
        const int id  = it * 128 + tid;
        const int row = id >> 2;
        const int seg = (id & 3) * 16;
        doff[it]  = row * (LDA * 2) + seg;
        goffA[it] = ((size_t)(m0 + row) * K) * 2 + seg;
        goffB[it] = ((size_t)(n0 + row) * K) * 2 + seg;
    }

    auto load_stage = [&](int s, int kc) {
        const uint32_t base = sb + s * STAGE_B;
        const size_t kb = (size_t)kc * (BK * 2);
        #pragma unroll
        for (int it = 0; it < 4; it++) {
            cp16(base + doff[it],         (const char*)A + goffA[it] + kb);
            cp16(base + MAT_T + doff[it], (const char*)B + goffB[it] + kb);
        }
        asm volatile("cp.async.commit_group;" ::: "memory");
    };

    wmma::fragment<wmma::accumulator, 16, 16, 16, float> acc[4][4];
    #pragma unroll
    for (int i = 0; i < 4; i++)
        #pragma unroll
        for (int j = 0; j < 4; j++)
            wmma::fill_fragment(acc[i][j], 0.0f);

    load_stage(0, 0);
    load_stage(1, 1);

    int stage = 0;
    for (int kt = 0; kt < NK; kt++) {
        asm volatile("cp.async.wait_group 1;" ::: "memory");
        __syncthreads();    // the only barrier per iteration

        const char* stg = smem + stage * STAGE_B;
        const __half* Ash = (const __half*)(stg);
        const __half* Bsh = (const __half*)(stg + MAT_T);

        #pragma unroll
        for (int ks = 0; ks < BK; ks += 16) {
            wmma::fragment<wmma::matrix_a, 16, 16, 16, __half, wmma::row_major> af[4];
            #pragma unroll
            for (int i = 0; i < 4; i++) {
                const int r = wm * 64 + i * 16;
                wmma::load_matrix_sync(af[i], Ash + r * LDA + ks, LDA);
            }
            #pragma unroll
            for (int j = 0; j < 4; j++) {
                wmma::fragment<wmma::matrix_b, 16, 16, 16, __half, wmma::col_major> bf;
                const int c = wn * 64 + j * 16;
                wmma::load_matrix_sync(bf, Bsh + c * LDA + ks, LDA);
                #pragma unroll
                for (int i = 0; i < 4; i++)
                    wmma::mma_sync(acc[i][j], af[i], bf, acc[i][j]);
            }
        }

        // load kt+2 into stage (kt+2)%3 — not being read by anyone now
        if (kt + 2 < NK) {
            int ls = stage + 2;
            if (ls >= NSTAGE) ls -= NSTAGE;
            load_stage(ls, kt + 2);
        } else {
            asm volatile("cp.async.commit_group;" ::: "memory");
        }

        if (++stage == NSTAGE) stage = 0;
    }

    // epilogue: frags -> smem (fp32, LDC=132), then bias add + coalesced store
    __syncthreads();
    float* Csh = (float*)smem;
    #pragma unroll
    for (int i = 0; i < 4; i++)
        #pragma unroll
        for (int j = 0; j < 4; j++)
            wmma::store_matrix_sync(
                Csh + (wm * 64 + i * 16) * LDC + wn * 64 + j * 16,
                acc[i][j], LDC, wmma::mem_row_major);
    __syncthreads();

    float4 bb = make_float4(0.f, 0.f, 0.f, 0.f);
    if (bias) bb = *(const float4*)(bias + n0 + lane * 4);
    #pragma unroll 4
    for (int i = 0; i < 32; i++) {
        const int r = wid * 32 + i;
        float4 v = *(const float4*)(Csh + r * LDC + lane * 4);
        v.x += bb.x; v.y += bb.y; v.z += bb.z; v.w += bb.w;
        *(float4*)(C + (size_t)(m0 + r) * N + n0 + lane * 4) = v;
    }
}

// ---------------------------------------------------------------------------
// Fused attention: SIMT + f32x2, 2 rows/thread, K(j+1) register rotation,
// V/bias prefetch, PACKED f32x2 reduction.  One block per (b,h),
// 128 threads (98 active), rows r and r+98.  Q pre-scaled into W_qkv.
// ---------------------------------------------------------------------------
#define ATT_THREADS 128
#define ATT_SMEM    ((2 * NSEQ * HDIM + 729) * (int)sizeof(float))   // 53092 B

__global__ __launch_bounds__(ATT_THREADS) void attention_kernel(
    const float* __restrict__ qkv,       // [12544, 3072]
    const float* __restrict__ rpk,       // [729, 32]
    __half* __restrict__ ath)            // [12544, 1024] fp16
{
    extern __shared__ float smf[];
    float* Ksh = smf;
    float* Vsh = smf + NSEQ * HDIM;
    float* rsh = smf + 2 * NSEQ * HDIM;

    const int h   = blockIdx.x;
    const int b   = blockIdx.y;
    const int tid = threadIdx.x;

    const float* base = qkv + (size_t)b * NSEQ * QKVN + h * HDIM;

    for (int f = tid; f < NSEQ * 8; f += ATT_THREADS) {
        const int j  = f >> 3;
        const int d4 = (f & 7) * 4;
        const size_t row = (size_t)j * QKVN;
        *(float4*)(Ksh + j * HDIM + d4) = *(const float4*)(base + row + CDIM   + d4);
        *(float4*)(Vsh + j * HDIM + d4) = *(const float4*)(base + row + 2*CDIM + d4);
    }
    for (int i = tid; i < 729; i += ATT_THREADS)
        rsh[i] = rpk[(size_t)i * HDIM + h];
    __syncthreads();

    if (tid < 98) {
        const int ra = tid;
        const int rb = tid + 98;

        unsigned long long qa[16], qb[16];
        #pragma unroll
        for (int d4 = 0; d4 < 8; d4++) {
            const float4 va = *(const float4*)(base + (size_t)ra * QKVN + d4 * 4);
            qa[d4 * 2 + 0] = pack2(va.x, va.y);
            qa[d4 * 2 + 1] = pack2(va.z, va.w);
            const float4 vb = *(const float4*)(base + (size_t)rb * QKVN + d4 * 4);
            qb[d4 * 2 + 0] = pack2(vb.x, vb.y);
            qb[d4 * 2 + 1] = pack2(vb.z, vb.w);
        }

        unsigned long long aa[16], ab[16];
        #pragma unroll
        for (int i = 0; i < 16; i++) { aa[i] = 0ull; ab[i] = 0ull; }
        float dena = 0.0f, denb = 0.0f;

        const int dyca = (ra / 14 + 13) * 27 + (ra % 14) + 13;
        const int dycb = (rb / 14 + 13) * 27 + (rb % 14) + 13;
        int t = 0, xj = 0;

        // preload K row 0
        ulonglong2 k0, k1, k2, k3, k4, k5, k6, k7;
        {
            const ulonglong2* kp = (const ulonglong2*)Ksh;
            k0 = kp[0]; k1 = kp[1]; k2 = kp[2]; k3 = kp[3];
            k4 = kp[4]; k5 = kp[5]; k6 = kp[6]; k7 = kp[7];
        }

        for (int j = 0; j < NSEQ; j++) {
            // bias prefetch (LDS latency hides under the QK fma stream)
            const float bia = rsh[dyca - t];
            const float bib = rsh[dycb - t];

            // QK for both rows on current K registers
            unsigned long long s0 = 0ull, s1 = 0ull, s2 = 0ull, s3 = 0ull;
            unsigned long long u0 = 0ull, u1 = 0ull, u2 = 0ull, u3 = 0ull;
            s0 = fma2(qa[0],  k0.x, s0);  u0 = fma2(qb[0],  k0.x, u0);
            s1 = fma2(qa[1],  k0.y, s1);  u1 = fma2(qb[1],  k0.y, u1);
            s2 = fma2(qa[2],  k1.x, s2);  u2 = fma2(qb[2],  k1.x, u2);
            s3 = fma2(qa[3],  k1.y, s3);  u3 = fma2(qb[3],  k1.y, u3);
            s0 = fma2(qa[4],  k2.x, s0);  u0 = fma2(qb[4],  k2.x, u0);
            s1 = fma2(qa[5],  k2.y, s1);  u1 = fma2(qb[5],  k2.y, u1);
            s2 = fma2(qa[6],  k3.x, s2);  u2 = fma2(qb[6],  k3.x, u2);
            s3 = fma2(qa[7],  k3.y, s3);  u3 = fma2(qb[7],  k3.y, u3);
            s0 = fma2(qa[8],  k4.x, s0);  u0 = fma2(qb[8],  k4.x, u0);
            s1 = fma2(qa[9],  k4.y, s1);  u1 = fma2(qb[9],  k4.y, u1);
            s2 = fma2(qa[10], k5.x, s2);  u2 = fma2(qb[10], k5.x, u2);
            s3 = fma2(qa[11], k5.y, s3);  u3 = fma2(qb[11], k5.y, u3);
            s0 = fma2(qa[12], k6.x, s0);  u0 = fma2(qb[12], k6.x, u0);
            s1 = fma2(qa[13], k6.y, s1);  u1 = fma2(qb[13], k6.y, u1);
            s2 = fma2(qa[14], k7.x, s2);  u2 = fma2(qb[14], k7.x, u2);
            s3 = fma2(qa[15], k7.y, s3);  u3 = fma2(qb[15], k7.y, u3);

            // prefetch V(j) and K(j+1) — latency overlaps the reduce/exp below
            const ulonglong2* vp = (const ulonglong2*)(Vsh + j * HDIM);
            const ulonglong2 v0 = vp[0], v1 = vp[1], v2 = vp[2], v3 = vp[3];
            const ulonglong2 v4 = vp[4], v5 = vp[5], v6 = vp[6], v7 = vp[7];
            const int jn = (j + 1 < NSEQ) ? (j + 1) : 0;
            const ulonglong2* kpn = (const ulonglong2*)(Ksh + jn * HDIM);
            const ulonglong2 n0 = kpn[0], n1 = kpn[1], n2 = kpn[2], n3 = kpn[3];
            const ulonglong2 n4 = kpn[4], n5 = kpn[5], n6 = kpn[6], n7 = kpn[7];

            // packed reduce + bias + exp
            s0 = add2(s0, s1); s2 = add2(s2, s3); s0 = add2(s0, s2);
            u0 = add2(u0, u1); u2 = add2(u2, u3); u0 = add2(u0, u2);
            const float2 fa = unpack2(s0);
            const float2 fb = unpack2(u0);
            const float pa = __expf((fa.x + fa.y) + bia);
            const float pb = __expf((fb.x + fb.y) + bib);
            dena += pa;
            denb += pb;
            const unsigned long long ppa = pack2(pa, pa);
            const unsigned long long ppb = pack2(pb, pb);

            // PV on prefetched V registers
            aa[0]  = fma2(ppa, v0.x, aa[0]);   ab[0]  = fma2(ppb, v0.x, ab[0]);
            aa[1]  = fma2(ppa, v0.y, aa[1]);   ab[1]  = fma2(ppb, v0.y, ab[1]);
            aa[2]  = fma2(ppa, v1.x, aa[2]);   ab[2]  = fma2(ppb, v1.x, ab[2]);
            aa[3]  = fma2(ppa, v1.y, aa[3]);   ab[3]  = fma2(ppb, v1.y, ab[3]);
            aa[4]  = fma2(ppa, v2.x, aa[4]);   ab[4]  = fma2(ppb, v2.x, ab[4]);
            aa[5]  = fma2(ppa, v2.y, aa[5]);   ab[5]  = fma2(ppb, v2.y, ab[5]);
            aa[6]  = fma2(ppa, v3.x, aa[6]);   ab[6]  = fma2(ppb, v3.x, ab[6]);
            aa[7]  = fma2(ppa, v3.y, aa[7]);   ab[7]  = fma2(ppb, v3.y, ab[7]);
            aa[8]  = fma2(ppa, v4.x, aa[8]);   ab[8]  = fma2(ppb, v4.x, ab[8]);
            aa[9]  = fma2(ppa, v4.y, aa[9]);   ab[9]  = fma2(ppb, v4.y, ab[9]);
            aa[10] = fma2(ppa, v5.x, aa[10]);  ab[10] = fma2(ppb, v5.x, ab[10]);
            aa[11] = fma2(ppa, v5.y, aa[11]);  ab[11] = fma2(ppb, v5.y, ab[11]);
            aa[12] = fma2(ppa, v6.x, aa[12]);  ab[12] = fma2(ppb, v6.x, ab[12]);
            aa[13] = fma2(ppa, v6.y, aa[13]);  ab[13] = fma2(ppb, v6.y, ab[13]);
            aa[14] = fma2(ppa, v7.x, aa[14]);  ab[14] = fma2(ppb, v7.x, ab[14]);
            aa[15] = fma2(ppa, v7.y, aa[15]);  ab[15] = fma2(ppb, v7.y, ab[15]);

            // rotate K registers
            k0 = n0; k1 = n1; k2 = n2; k3 = n3;
            k4 = n4; k5 = n5; k6 = n6; k7 = n7;

            t++;
            if (++xj == 14) { xj = 0; t += 13; }
        }

        const float inva = 1.0f / dena;
        const float invb = 1.0f / denb;
        __half* oa = ath + (size_t)(b * NSEQ + ra) * CDIM + h * HDIM;
        __half* ob = ath + (size_t)(b * NSEQ + rb) * CDIM + h * HDIM;
        #pragma unroll
        for (int i = 0; i < 16; i++) {
            const float2 o1 = unpack2(aa[i]);
            *(__half2*)(oa + i * 2) = __halves2half2(
                __float2half(o1.x * inva), __float2half(o1.y * inva));
            const float2 o2 = unpack2(ab[i]);
            *(__half2*)(ob + i * 2) = __halves2half2(
                __float2half(o2.x * invb), __float2half(o2.y * invb));
        }
    }
}

// ---------------------------------------------------------------------------
// Launch
// ---------------------------------------------------------------------------
extern "C" void kernel_launch(void* const* d_in, const int* in_sizes, int n_in,
                              void* d_out, int out_size)
{
    const float* x      = (const float*)d_in[0];
    const float* W_qkv  = (const float*)d_in[1];
    const float* W_proj = (const float*)d_in[2];
    const float* b_proj = (const float*)d_in[3];
    const float* rpk    = (const float*)d_in[4];
    float* out = (float*)d_out;

    float *qkv;
    __half *xh, *wqh, *wph, *ath;
    cudaGetSymbolAddress((void**)&qkv, g_qkv);
    cudaGetSymbolAddress((void**)&xh,  g_xh);
    cudaGetSymbolAddress((void**)&wqh, g_wqh);
    cudaGetSymbolAddress((void**)&wph, g_wph);
    cudaGetSymbolAddress((void**)&ath, g_ath);

    cudaFuncSetAttribute(gemm_fp16,
                         cudaFuncAttributeMaxDynamicSharedMemorySize, GEMM_SMEM);
    cudaFuncSetAttribute(attention_kernel,
                         cudaFuncAttributeMaxDynamicSharedMemorySize, ATT_SMEM);

    // 0) fused conversions (single launch)
    fused_convert_kernel<<<NB_CVT + NB_TQ + NB_TP, 256>>>(
        x, xh, W_qkv, wqh, W_proj, wph);

    // 1) QKV projection: [12544,1024] x [1024,3072]
    gemm_fp16<<<dim3(QKVN / 128, MROWS / 128), 128, GEMM_SMEM>>>(
        xh, wqh, qkv, nullptr, MROWS, QKVN, CDIM);

    // 2) SIMT f32x2 attention per (b,h), 2 rows/thread, k-rotation pipeline
    attention_kernel<<<dim3(NHEAD, BATCH), ATT_THREADS, ATT_SMEM>>>(qkv, rpk, ath);

    // 3) output projection: [12544,1024] x [1024,1024] + bias
    gemm_fp16<<<dim3(CDIM / 128, MROWS / 128), 128, GEMM_SMEM>>>(
        ath, wph, out, b_proj, MROWS, CDIM, CDIM);
}